// round 5
// baseline (speedup 1.0000x reference)
#include <cuda_runtime.h>
#include <cstdint>

#define B_    8192
#define T_    90
#define F_    7
#define H_    128
#define G_    512      // 4*H
#define D1_   128
#define D2_   64
#define OUT_  30
#define KTOT  256      // H (x part) + H (h part)

// -------- device scratch (no cudaMalloc allowed) --------
__device__ float g_hin  [B_ * T_ * H_];   // LN(x@W_in^T+b) : layer-0 input
__device__ float g_hout0[B_ * T_ * H_];   // layer-0 hidden outputs
__device__ float g_WT   [2 * KTOT * G_];  // K-major packed [Wih|Whh] per layer
__device__ float g_biasC[2 * G_];         // bih + bhh per layer

// -------- helpers --------
__device__ __forceinline__ float sgf(float x) {
    return __fdividef(1.0f, 1.0f + __expf(-x));
}
__device__ __forceinline__ float thf(float x) {
    return 2.0f * sgf(2.0f * x) - 1.0f;
}
__device__ __forceinline__ unsigned long long pk2(float x) {
    unsigned long long r;
    asm("mov.b64 %0, {%1, %1};" : "=l"(r) : "f"(x));
    return r;
}
__device__ __forceinline__ unsigned long long pkab(float a, float b) {
    unsigned long long r;
    asm("mov.b64 %0, {%1, %2};" : "=l"(r) : "f"(a), "f"(b));
    return r;
}
__device__ __forceinline__ void up2(unsigned long long v, float& a, float& b) {
    asm("mov.b64 {%0, %1}, %2;" : "=f"(a), "=f"(b) : "l"(v));
}
// packed dual fp32 FMA (sm_100+): d = a*b + d  (lane-wise on the two f32 halves)
__device__ __forceinline__ void fma2(unsigned long long& d,
                                     unsigned long long a, unsigned long long b) {
    asm("fma.rn.f32x2 %0, %1, %2, %0;" : "+l"(d) : "l"(a), "l"(b));
}
__device__ __forceinline__ void cpa16(uint32_t s, const void* g) {
    asm volatile("cp.async.cg.shared.global [%0], [%1], 16;" :: "r"(s), "l"(g));
}
__device__ __forceinline__ void cpcommit() { asm volatile("cp.async.commit_group;"); }
__device__ __forceinline__ void cpwait0()  { asm volatile("cp.async.wait_group 0;"); }

// ======================= K0: weight repack =======================
__global__ void prep_kernel(const float* __restrict__ Wih0, const float* __restrict__ Whh0,
                            const float* __restrict__ bih0, const float* __restrict__ bhh0,
                            const float* __restrict__ Wih1, const float* __restrict__ Whh1,
                            const float* __restrict__ bih1, const float* __restrict__ bhh1) {
    int idx = blockIdx.x * blockDim.x + threadIdx.x;
    int tot = 2 * KTOT * G_;
    if (idx < tot) {
        int L = idx / (KTOT * G_);
        int r = idx % (KTOT * G_);
        int k = r / G_;
        int n = r % G_;
        const float* Wih = L ? Wih1 : Wih0;
        const float* Whh = L ? Whh1 : Whh0;
        g_WT[idx] = (k < H_) ? Wih[n * H_ + k] : Whh[n * H_ + (k - H_)];
    }
    if (idx < 2 * G_) {
        int L = idx / G_;
        int n = idx % G_;
        g_biasC[idx] = L ? (bih1[n] + bhh1[n]) : (bih0[n] + bhh0[n]);
    }
}

// ============ K1: input projection + layernorm (warp per row) ============
__global__ void __launch_bounds__(256) proj_ln_kernel(
    const float* __restrict__ x, const float* __restrict__ W_in,
    const float* __restrict__ b_in, const float* __restrict__ g_in,
    const float* __restrict__ be_in) {
    __shared__ float Ws[H_ * F_];
    __shared__ float bs[H_], gs[H_], es[H_];
    int tid = threadIdx.x;
    for (int i = tid; i < H_ * F_; i += 256) Ws[i] = W_in[i];
    if (tid < H_) { bs[tid] = b_in[tid]; gs[tid] = g_in[tid]; es[tid] = be_in[tid]; }
    __syncthreads();

    int warp = tid >> 5, lane = tid & 31;
    int row = blockIdx.x * 8 + warp;        // row < B*T = 737280

    float xv = (lane < F_) ? x[row * F_ + lane] : 0.0f;
    float y[4];
#pragma unroll
    for (int j = 0; j < 4; j++) {
        int h = lane + 32 * j;
        float a = bs[h];
#pragma unroll
        for (int f = 0; f < F_; f++) {
            float xf = __shfl_sync(0xffffffffu, xv, f);
            a = fmaf(xf, Ws[h * F_ + f], a);
        }
        y[j] = a;
    }
    float s = y[0] + y[1] + y[2] + y[3];
#pragma unroll
    for (int o = 16; o; o >>= 1) s += __shfl_xor_sync(0xffffffffu, s, o);
    float mu = s * (1.0f / H_);
    float v = 0.0f;
#pragma unroll
    for (int j = 0; j < 4; j++) { float d = y[j] - mu; v += d * d; }
#pragma unroll
    for (int o = 16; o; o >>= 1) v += __shfl_xor_sync(0xffffffffu, v, o);
    float rstd = rsqrtf(v * (1.0f / H_) + 1e-5f);
#pragma unroll
    for (int j = 0; j < 4; j++) {
        int h = lane + 32 * j;
        g_hin[row * H_ + h] = (y[j] - mu) * rstd * gs[h] + es[h];
    }
}

// ============ K2: persistent 2-layer LSTM + LN + dense head ============
// 128 CTAs x 256 threads; each CTA owns 64 batch rows end-to-end.
// smem layout (dynamic):
//   [0, 65536)            aT      : float[256][64]  (k-major activations: x | h)
//   [65536, 196608)       wbuf0/1 : two 32x512 float weight chunks
//   [196608, 198656)      biasS   : float[512]
// dense-phase reuse inside the wbuf region.
#define OFF_AT   0
#define OFF_W0   65536
#define OFF_W1   (65536 + 65536)
#define OFF_BIAS 196608
#define SMEM_BYTES 198656

__global__ void __launch_bounds__(256, 1) lstm_kernel(
    const float* __restrict__ g_ln, const float* __restrict__ be_ln,
    const float* __restrict__ W_d1, const float* __restrict__ b_d1,
    const float* __restrict__ W_d2, const float* __restrict__ b_d2,
    const float* __restrict__ W_d3, const float* __restrict__ b_d3,
    float* __restrict__ out) {
    extern __shared__ char smem[];
    float* aT    = (float*)(smem + OFF_AT);
    float* wbuf0 = (float*)(smem + OFF_W0);
    float* wbuf1 = (float*)(smem + OFF_W1);
    float* biasS = (float*)(smem + OFF_BIAS);

    const int tid = threadIdx.x;
    const int tr  = tid & 15;   // row group: rows 4*tr .. 4*tr+3
    const int tc  = tid >> 4;   // 0..15: cols [tc*8, tc*8+8) within each gate
    const int row0 = blockIdx.x * 64;

    uint32_t wsmAddr[2];
    wsmAddr[0] = (uint32_t)__cvta_generic_to_shared(wbuf0);
    wsmAddr[1] = (uint32_t)__cvta_generic_to_shared(wbuf1);

    unsigned long long c2[4][4];        // cell state pairs (regs)
    unsigned long long acc[4][4][4];    // gate accum: [row][gate][pair]

    for (int layer = 0; layer < 2; ++layer) {
        const float* xin = layer ? g_hout0 : g_hin;
        const float* WT  = g_WT + layer * (KTOT * G_);

        __syncthreads();    // previous phase fully done before reinit
        for (int i = tid; i < G_; i += 256) biasS[i] = g_biasC[layer * G_ + i];
        for (int i = tid; i < H_ * 64; i += 256) aT[H_ * 64 + i] = 0.0f;  // h = 0
#pragma unroll
        for (int i = 0; i < 4; i++)
#pragma unroll
            for (int p = 0; p < 4; p++) c2[i][p] = 0ull;

        for (int t = 0; t < T_; ++t) {
            __syncthreads();   // A: prior-step readers/writers done
            // ---- load x_t transposed into aT[0..127][row] ----
            {
                int r = tid >> 2;
                int seg = (tid & 3) * 32;
                const float* src = xin + ((row0 + r) * T_ + t) * H_ + seg;
#pragma unroll
                for (int j = 0; j < 8; j++) {
                    float4 v = *(const float4*)(src + j * 4);
                    int k = seg + j * 4;
                    aT[(k + 0) * 64 + r] = v.x;
                    aT[(k + 1) * 64 + r] = v.y;
                    aT[(k + 2) * 64 + r] = v.z;
                    aT[(k + 3) * 64 + r] = v.w;
                }
            }
            __syncthreads();   // B: x ready

#pragma unroll
            for (int i = 0; i < 4; i++)
#pragma unroll
                for (int g = 0; g < 4; g++)
#pragma unroll
                    for (int p = 0; p < 4; p++) acc[i][g][p] = 0ull;

            // ---- K loop: 8 chunks of 32 k-values, double-buffered cp.async ----
            auto issue_copy = [&](int ck) {
                const float* src = WT + ck * (32 * G_);
                uint32_t sb = wsmAddr[ck & 1];
#pragma unroll
                for (int j = 0; j < 16; j++) {
                    int u = tid + 256 * j;
                    cpa16(sb + u * 16, src + u * 4);
                }
                cpcommit();
            };
            issue_copy(0);
            const int tc2 = tc * 2;
            for (int ck = 0; ck < 8; ++ck) {
                cpwait0();
                __syncthreads();
                if (ck < 7) issue_copy(ck + 1);
                const float* wb  = (ck & 1) ? wbuf1 : wbuf0;
                const float* aTk = aT + ck * (32 * 64);
#pragma unroll 4
                for (int kk = 0; kk < 32; ++kk) {
                    const float4 a4 = *(const float4*)(aTk + kk * 64 + tr * 4);
                    unsigned long long a2[4] = {pk2(a4.x), pk2(a4.y), pk2(a4.z), pk2(a4.w)};
                    const ulonglong2* wr = (const ulonglong2*)(wb + kk * G_);
#pragma unroll
                    for (int g = 0; g < 4; ++g) {
                        ulonglong2 wA = wr[g * 32 + tc2];
                        ulonglong2 wB = wr[g * 32 + tc2 + 1];
#pragma unroll
                        for (int i = 0; i < 4; ++i) {
                            fma2(acc[i][g][0], a2[i], wA.x);
                            fma2(acc[i][g][1], a2[i], wA.y);
                            fma2(acc[i][g][2], a2[i], wB.x);
                            fma2(acc[i][g][3], a2[i], wB.y);
                        }
                    }
                }
            }
            __syncthreads();   // all GEMM reads of aT done before h overwrite

            // ---- activations + state update (regs) ----
            const unsigned long long* b2 = (const unsigned long long*)biasS;
#pragma unroll
            for (int i = 0; i < 4; i++) {
                int r = tr * 4 + i;
                float hv[8];
#pragma unroll
                for (int p = 0; p < 4; p++) {
                    int pi = tc * 4 + p;    // pair index within a gate (col = 2*pi)
                    float iv0, iv1, fv0, fv1, gv0, gv1, ov0, ov1, b0, b1;
                    up2(acc[i][0][p], iv0, iv1); up2(b2[0 * 64 + pi], b0, b1); iv0 += b0; iv1 += b1;
                    up2(acc[i][1][p], fv0, fv1); up2(b2[1 * 64 + pi], b0, b1); fv0 += b0; fv1 += b1;
                    up2(acc[i][2][p], gv0, gv1); up2(b2[2 * 64 + pi], b0, b1); gv0 += b0; gv1 += b1;
                    up2(acc[i][3][p], ov0, ov1); up2(b2[3 * 64 + pi], b0, b1); ov0 += b0; ov1 += b1;
                    float c0, c1;
                    up2(c2[i][p], c0, c1);
                    c0 = sgf(fv0) * c0 + sgf(iv0) * thf(gv0);
                    c1 = sgf(fv1) * c1 + sgf(iv1) * thf(gv1);
                    c2[i][p] = pkab(c0, c1);
                    float h0 = sgf(ov0) * thf(c0);
                    float h1 = sgf(ov1) * thf(c1);
                    int col = tc * 8 + 2 * p;
                    aT[(H_ + col) * 64 + r]     = h0;
                    aT[(H_ + col + 1) * 64 + r] = h1;
                    hv[2 * p] = h0; hv[2 * p + 1] = h1;
                }
                if (layer == 0) {
                    float* dst = g_hout0 + ((row0 + r) * T_ + t) * H_ + tc * 8;
                    *(float4*)(dst)     = make_float4(hv[0], hv[1], hv[2], hv[3]);
                    *(float4*)(dst + 4) = make_float4(hv[4], hv[5], hv[6], hv[7]);
                }
            }
        } // t
    } // layer

    // =================== dense head (final h lives in aT) ===================
    __syncthreads();
    float* lnS = (float*)(smem + OFF_W0);                 // [64][128]
    float* d1S = (float*)(smem + OFF_W0 + 32768);         // [64][128]
    float* wdS = (float*)(smem + OFF_W0 + 65536);         // weight staging (64KB)
    float* d2S = lnS;                                     // reuse after LN dead

    // LayerNorm of last hidden state
    if (tid < 64) {
        int r = tid;
        float s = 0.0f;
        for (int k = 0; k < H_; k++) s += aT[(H_ + k) * 64 + r];
        float mu = s * (1.0f / H_);
        float v = 0.0f;
        for (int k = 0; k < H_; k++) { float d = aT[(H_ + k) * 64 + r] - mu; v += d * d; }
        float rstd = rsqrtf(v * (1.0f / H_) + 1e-5f);
        for (int k = 0; k < H_; k++)
            lnS[r * H_ + k] = (aT[(H_ + k) * 64 + r] - mu) * rstd * __ldg(g_ln + k) + __ldg(be_ln + k);
    }
    for (int i = tid; i < D1_ * H_ / 4; i += 256)
        ((float4*)wdS)[i] = ((const float4*)W_d1)[i];
    __syncthreads();

    // d1 = relu(ln @ W_d1^T + b_d1)
    {
        int r = tid >> 2, c0 = (tid & 3) * 32;
        for (int c = c0; c < c0 + 32; c++) {
            float a = __ldg(b_d1 + c);
            const float4* lp = (const float4*)(lnS + r * H_);
            const float4* wp = (const float4*)(wdS + c * H_);
#pragma unroll 8
            for (int k4 = 0; k4 < H_ / 4; k4++) {
                float4 l = lp[k4], w = wp[k4];
                a = fmaf(l.x, w.x, fmaf(l.y, w.y, fmaf(l.z, w.z, fmaf(l.w, w.w, a))));
            }
            d1S[r * D1_ + c] = fmaxf(a, 0.0f);
        }
    }
    __syncthreads();
    for (int i = tid; i < D2_ * D1_ / 4; i += 256)
        ((float4*)wdS)[i] = ((const float4*)W_d2)[i];
    float* w3S = wdS + D2_ * D1_;
    for (int i = tid; i < OUT_ * D2_; i += 256) w3S[i] = W_d3[i];
    __syncthreads();

    // d2 = relu(d1 @ W_d2^T + b_d2)
    {
        int r = tid >> 2, c0 = (tid & 3) * 16;
        for (int c = c0; c < c0 + 16; c++) {
            float a = __ldg(b_d2 + c);
            const float4* dp = (const float4*)(d1S + r * D1_);
            const float4* wp = (const float4*)(wdS + c * D1_);
#pragma unroll 8
            for (int k4 = 0; k4 < D1_ / 4; k4++) {
                float4 l = dp[k4], w = wp[k4];
                a = fmaf(l.x, w.x, fmaf(l.y, w.y, fmaf(l.z, w.z, fmaf(l.w, w.w, a))));
            }
            d2S[r * D2_ + c] = fmaxf(a, 0.0f);
        }
    }
    __syncthreads();

    // out = d2 @ W_d3^T + b_d3
    for (int idx = tid; idx < 64 * OUT_; idx += 256) {
        int r = idx / OUT_, c = idx % OUT_;
        float a = __ldg(b_d3 + c);
        const float* dp = d2S + r * D2_;
        const float* wp = w3S + c * D2_;
#pragma unroll 8
        for (int k = 0; k < D2_; k++) a = fmaf(dp[k], wp[k], a);
        out[(row0 + r) * OUT_ + c] = a;
    }
}

// ======================= launch =======================
extern "C" void kernel_launch(void* const* d_in, const int* in_sizes, int n_in,
                              void* d_out, int out_size) {
    (void)in_sizes; (void)n_in; (void)out_size;
    const float* x     = (const float*)d_in[0];
    const float* W_in  = (const float*)d_in[1];
    const float* b_in  = (const float*)d_in[2];
    const float* g_in  = (const float*)d_in[3];
    const float* be_in = (const float*)d_in[4];
    const float* Wih0  = (const float*)d_in[5];
    const float* Whh0  = (const float*)d_in[6];
    const float* bih0  = (const float*)d_in[7];
    const float* bhh0  = (const float*)d_in[8];
    const float* Wih1  = (const float*)d_in[9];
    const float* Whh1  = (const float*)d_in[10];
    const float* bih1  = (const float*)d_in[11];
    const float* bhh1  = (const float*)d_in[12];
    const float* g_ln  = (const float*)d_in[13];
    const float* be_ln = (const float*)d_in[14];
    const float* W_d1  = (const float*)d_in[15];
    const float* b_d1  = (const float*)d_in[16];
    const float* W_d2  = (const float*)d_in[17];
    const float* b_d2  = (const float*)d_in[18];
    const float* W_d3  = (const float*)d_in[19];
    const float* b_d3  = (const float*)d_in[20];
    float* out = (float*)d_out;

    prep_kernel<<<1024, 256>>>(Wih0, Whh0, bih0, bhh0, Wih1, Whh1, bih1, bhh1);
    proj_ln_kernel<<<(B_ * T_) / 8, 256>>>(x, W_in, b_in, g_in, be_in);
    cudaFuncSetAttribute(lstm_kernel, cudaFuncAttributeMaxDynamicSharedMemorySize, SMEM_BYTES);
    lstm_kernel<<<B_ / 64, 256, SMEM_BYTES>>>(g_ln, be_ln, W_d1, b_d1, W_d2, b_d2,
                                              W_d3, b_d3, out);
}

// round 6
// speedup vs baseline: 1.0603x; 1.0603x over previous
#include <cuda_runtime.h>
#include <cstdint>

#define B_    8192
#define T_    90
#define F_    7
#define H_    128
#define G_    512      // 4*H
#define D1_   128
#define D2_   64
#define OUT_  30
#define KTOT  256      // H (x part) + H (h part)

// -------- device scratch (no cudaMalloc allowed) --------
__device__ float g_hin  [B_ * T_ * H_];   // LN(x@W_in^T+b) : layer-0 input
__device__ float g_hout0[B_ * T_ * H_];   // layer-0 hidden outputs
__device__ float g_WT   [2 * KTOT * G_];  // K-major packed [Wih|Whh] per layer
__device__ float g_biasC[2 * G_];         // bih + bhh per layer

// -------- helpers --------
__device__ __forceinline__ float sgf(float x) {
    return __fdividef(1.0f, 1.0f + __expf(-x));
}
__device__ __forceinline__ float thf(float x) {
    return 2.0f * sgf(2.0f * x) - 1.0f;
}
__device__ __forceinline__ unsigned long long pk2(float x) {
    unsigned long long r;
    asm("mov.b64 %0, {%1, %1};" : "=l"(r) : "f"(x));
    return r;
}
__device__ __forceinline__ unsigned long long pkab(float a, float b) {
    unsigned long long r;
    asm("mov.b64 %0, {%1, %2};" : "=l"(r) : "f"(a), "f"(b));
    return r;
}
__device__ __forceinline__ void up2(unsigned long long v, float& a, float& b) {
    asm("mov.b64 {%0, %1}, %2;" : "=f"(a), "=f"(b) : "l"(v));
}
// packed dual fp32 FMA (sm_100+): d = a*b + d  (lane-wise on the two f32 halves)
__device__ __forceinline__ void fma2(unsigned long long& d,
                                     unsigned long long a, unsigned long long b) {
    asm("fma.rn.f32x2 %0, %1, %2, %0;" : "+l"(d) : "l"(a), "l"(b));
}
__device__ __forceinline__ void cpa16(uint32_t s, const void* g) {
    asm volatile("cp.async.cg.shared.global [%0], [%1], 16;" :: "r"(s), "l"(g));
}
__device__ __forceinline__ void cpcommit() { asm volatile("cp.async.commit_group;"); }
__device__ __forceinline__ void cpwait0()  { asm volatile("cp.async.wait_group 0;"); }

// ======================= K0: weight repack =======================
__global__ void prep_kernel(const float* __restrict__ Wih0, const float* __restrict__ Whh0,
                            const float* __restrict__ bih0, const float* __restrict__ bhh0,
                            const float* __restrict__ Wih1, const float* __restrict__ Whh1,
                            const float* __restrict__ bih1, const float* __restrict__ bhh1) {
    int idx = blockIdx.x * blockDim.x + threadIdx.x;
    int tot = 2 * KTOT * G_;
    if (idx < tot) {
        int L = idx / (KTOT * G_);
        int r = idx % (KTOT * G_);
        int k = r / G_;
        int n = r % G_;
        const float* Wih = L ? Wih1 : Wih0;
        const float* Whh = L ? Whh1 : Whh0;
        g_WT[idx] = (k < H_) ? Wih[n * H_ + k] : Whh[n * H_ + (k - H_)];
    }
    if (idx < 2 * G_) {
        int L = idx / G_;
        int n = idx % G_;
        g_biasC[idx] = L ? (bih1[n] + bhh1[n]) : (bih0[n] + bhh0[n]);
    }
}

// ============ K1: input projection + layernorm (warp per row) ============
__global__ void __launch_bounds__(256) proj_ln_kernel(
    const float* __restrict__ x, const float* __restrict__ W_in,
    const float* __restrict__ b_in, const float* __restrict__ g_in,
    const float* __restrict__ be_in) {
    __shared__ float Ws[H_ * F_];
    __shared__ float bs[H_], gs[H_], es[H_];
    int tid = threadIdx.x;
    for (int i = tid; i < H_ * F_; i += 256) Ws[i] = W_in[i];
    if (tid < H_) { bs[tid] = b_in[tid]; gs[tid] = g_in[tid]; es[tid] = be_in[tid]; }
    __syncthreads();

    int warp = tid >> 5, lane = tid & 31;
    int row = blockIdx.x * 8 + warp;        // row < B*T = 737280

    float xv = (lane < F_) ? x[row * F_ + lane] : 0.0f;
    float y[4];
#pragma unroll
    for (int j = 0; j < 4; j++) {
        int h = lane + 32 * j;
        float a = bs[h];
#pragma unroll
        for (int f = 0; f < F_; f++) {
            float xf = __shfl_sync(0xffffffffu, xv, f);
            a = fmaf(xf, Ws[h * F_ + f], a);
        }
        y[j] = a;
    }
    float s = y[0] + y[1] + y[2] + y[3];
#pragma unroll
    for (int o = 16; o; o >>= 1) s += __shfl_xor_sync(0xffffffffu, s, o);
    float mu = s * (1.0f / H_);
    float v = 0.0f;
#pragma unroll
    for (int j = 0; j < 4; j++) { float d = y[j] - mu; v += d * d; }
#pragma unroll
    for (int o = 16; o; o >>= 1) v += __shfl_xor_sync(0xffffffffu, v, o);
    float rstd = rsqrtf(v * (1.0f / H_) + 1e-5f);
#pragma unroll
    for (int j = 0; j < 4; j++) {
        int h = lane + 32 * j;
        g_hin[row * H_ + h] = (y[j] - mu) * rstd * gs[h] + es[h];
    }
}

// ============ K2: persistent 2-layer LSTM + LN + dense head ============
// 128 CTAs x 256 threads; each CTA owns 64 batch rows end-to-end.
// smem layout (dynamic):
//   [0, 65536)            aT      : float[256][64]  (k-major activations: x | h)
//   [65536, 196608)       wbuf0/1 : two 32x512 float weight chunks
//   [196608, 198656)      biasS   : float[512]
// dense-phase reuse inside the wbuf region.
#define OFF_AT   0
#define OFF_W0   65536
#define OFF_W1   (65536 + 65536)
#define OFF_BIAS 196608
#define SMEM_BYTES 198656

__global__ void __launch_bounds__(256, 1) lstm_kernel(
    const float* __restrict__ g_ln, const float* __restrict__ be_ln,
    const float* __restrict__ W_d1, const float* __restrict__ b_d1,
    const float* __restrict__ W_d2, const float* __restrict__ b_d2,
    const float* __restrict__ W_d3, const float* __restrict__ b_d3,
    float* __restrict__ out) {
    extern __shared__ char smem[];
    float* aT    = (float*)(smem + OFF_AT);
    float* wbuf0 = (float*)(smem + OFF_W0);
    float* wbuf1 = (float*)(smem + OFF_W1);
    float* biasS = (float*)(smem + OFF_BIAS);

    const int tid = threadIdx.x;
    const int tr  = tid & 15;   // row group: rows 4*tr .. 4*tr+3
    const int tc  = tid >> 4;   // 0..15: cols [tc*8, tc*8+8) within each gate
    const int row0 = blockIdx.x * 64;

    uint32_t wsmAddr[2];
    wsmAddr[0] = (uint32_t)__cvta_generic_to_shared(wbuf0);
    wsmAddr[1] = (uint32_t)__cvta_generic_to_shared(wbuf1);

    unsigned long long c2[4][4];        // cell state pairs (regs)
    unsigned long long acc[4][4][4];    // gate accum: [row][gate][pair]

    for (int layer = 0; layer < 2; ++layer) {
        const float* xin = layer ? g_hout0 : g_hin;
        const float* WT  = g_WT + layer * (KTOT * G_);

        __syncthreads();    // previous phase fully done before reinit
        for (int i = tid; i < G_; i += 256) biasS[i] = g_biasC[layer * G_ + i];
        for (int i = tid; i < H_ * 64; i += 256) aT[H_ * 64 + i] = 0.0f;  // h = 0
#pragma unroll
        for (int i = 0; i < 4; i++)
#pragma unroll
            for (int p = 0; p < 4; p++) c2[i][p] = 0ull;

        for (int t = 0; t < T_; ++t) {
            __syncthreads();   // A: prior-step readers/writers done
            // ---- load x_t transposed into aT[0..127][row] ----
            {
                int r = tid >> 2;
                int seg = (tid & 3) * 32;
                const float* src = xin + ((row0 + r) * T_ + t) * H_ + seg;
#pragma unroll
                for (int j = 0; j < 8; j++) {
                    float4 v = *(const float4*)(src + j * 4);
                    int k = seg + j * 4;
                    aT[(k + 0) * 64 + r] = v.x;
                    aT[(k + 1) * 64 + r] = v.y;
                    aT[(k + 2) * 64 + r] = v.z;
                    aT[(k + 3) * 64 + r] = v.w;
                }
            }
            __syncthreads();   // B: x ready

#pragma unroll
            for (int i = 0; i < 4; i++)
#pragma unroll
                for (int g = 0; g < 4; g++)
#pragma unroll
                    for (int p = 0; p < 4; p++) acc[i][g][p] = 0ull;

            // ---- K loop: 8 chunks of 32 k-values, double-buffered cp.async ----
            auto issue_copy = [&](int ck) {
                const float* src = WT + ck * (32 * G_);
                uint32_t sb = wsmAddr[ck & 1];
#pragma unroll
                for (int j = 0; j < 16; j++) {
                    int u = tid + 256 * j;
                    cpa16(sb + u * 16, src + u * 4);
                }
                cpcommit();
            };
            issue_copy(0);
            const int tc2 = tc * 2;
            for (int ck = 0; ck < 8; ++ck) {
                cpwait0();
                __syncthreads();
                if (ck < 7) issue_copy(ck + 1);
                const float* wb  = (ck & 1) ? wbuf1 : wbuf0;
                const float* aTk = aT + ck * (32 * 64);
#pragma unroll 4
                for (int kk = 0; kk < 32; ++kk) {
                    const float4 a4 = *(const float4*)(aTk + kk * 64 + tr * 4);
                    unsigned long long a2[4] = {pk2(a4.x), pk2(a4.y), pk2(a4.z), pk2(a4.w)};
                    const ulonglong2* wr = (const ulonglong2*)(wb + kk * G_);
#pragma unroll
                    for (int g = 0; g < 4; ++g) {
                        ulonglong2 wA = wr[g * 32 + tc2];
                        ulonglong2 wB = wr[g * 32 + tc2 + 1];
#pragma unroll
                        for (int i = 0; i < 4; ++i) {
                            fma2(acc[i][g][0], a2[i], wA.x);
                            fma2(acc[i][g][1], a2[i], wA.y);
                            fma2(acc[i][g][2], a2[i], wB.x);
                            fma2(acc[i][g][3], a2[i], wB.y);
                        }
                    }
                }
            }
            __syncthreads();   // all GEMM reads of aT done before h overwrite

            // ---- activations + state update (regs) ----
            const unsigned long long* b2 = (const unsigned long long*)biasS;
#pragma unroll
            for (int i = 0; i < 4; i++) {
                int r = tr * 4 + i;
                float hv[8];
#pragma unroll
                for (int p = 0; p < 4; p++) {
                    int pi = tc * 4 + p;    // pair index within a gate (col = 2*pi)
                    float iv0, iv1, fv0, fv1, gv0, gv1, ov0, ov1, b0, b1;
                    up2(acc[i][0][p], iv0, iv1); up2(b2[0 * 64 + pi], b0, b1); iv0 += b0; iv1 += b1;
                    up2(acc[i][1][p], fv0, fv1); up2(b2[1 * 64 + pi], b0, b1); fv0 += b0; fv1 += b1;
                    up2(acc[i][2][p], gv0, gv1); up2(b2[2 * 64 + pi], b0, b1); gv0 += b0; gv1 += b1;
                    up2(acc[i][3][p], ov0, ov1); up2(b2[3 * 64 + pi], b0, b1); ov0 += b0; ov1 += b1;
                    float c0, c1;
                    up2(c2[i][p], c0, c1);
                    c0 = sgf(fv0) * c0 + sgf(iv0) * thf(gv0);
                    c1 = sgf(fv1) * c1 + sgf(iv1) * thf(gv1);
                    c2[i][p] = pkab(c0, c1);
                    float h0 = sgf(ov0) * thf(c0);
                    float h1 = sgf(ov1) * thf(c1);
                    int col = tc * 8 + 2 * p;
                    aT[(H_ + col) * 64 + r]     = h0;
                    aT[(H_ + col + 1) * 64 + r] = h1;
                    hv[2 * p] = h0; hv[2 * p + 1] = h1;
                }
                if (layer == 0) {
                    float* dst = g_hout0 + ((row0 + r) * T_ + t) * H_ + tc * 8;
                    *(float4*)(dst)     = make_float4(hv[0], hv[1], hv[2], hv[3]);
                    *(float4*)(dst + 4) = make_float4(hv[4], hv[5], hv[6], hv[7]);
                }
            }
        } // t
    } // layer

    // =================== dense head (final h lives in aT) ===================
    __syncthreads();
    float* lnS = (float*)(smem + OFF_W0);                 // [64][128]
    float* d1S = (float*)(smem + OFF_W0 + 32768);         // [64][128]
    float* wdS = (float*)(smem + OFF_W0 + 65536);         // weight staging (64KB)
    float* d2S = lnS;                                     // reuse after LN dead

    // LayerNorm of last hidden state
    if (tid < 64) {
        int r = tid;
        float s = 0.0f;
        for (int k = 0; k < H_; k++) s += aT[(H_ + k) * 64 + r];
        float mu = s * (1.0f / H_);
        float v = 0.0f;
        for (int k = 0; k < H_; k++) { float d = aT[(H_ + k) * 64 + r] - mu; v += d * d; }
        float rstd = rsqrtf(v * (1.0f / H_) + 1e-5f);
        for (int k = 0; k < H_; k++)
            lnS[r * H_ + k] = (aT[(H_ + k) * 64 + r] - mu) * rstd * __ldg(g_ln + k) + __ldg(be_ln + k);
    }
    for (int i = tid; i < D1_ * H_ / 4; i += 256)
        ((float4*)wdS)[i] = ((const float4*)W_d1)[i];
    __syncthreads();

    // d1 = relu(ln @ W_d1^T + b_d1)
    {
        int r = tid >> 2, c0 = (tid & 3) * 32;
        for (int c = c0; c < c0 + 32; c++) {
            float a = __ldg(b_d1 + c);
            const float4* lp = (const float4*)(lnS + r * H_);
            const float4* wp = (const float4*)(wdS + c * H_);
#pragma unroll 8
            for (int k4 = 0; k4 < H_ / 4; k4++) {
                float4 l = lp[k4], w = wp[k4];
                a = fmaf(l.x, w.x, fmaf(l.y, w.y, fmaf(l.z, w.z, fmaf(l.w, w.w, a))));
            }
            d1S[r * D1_ + c] = fmaxf(a, 0.0f);
        }
    }
    __syncthreads();
    for (int i = tid; i < D2_ * D1_ / 4; i += 256)
        ((float4*)wdS)[i] = ((const float4*)W_d2)[i];
    float* w3S = wdS + D2_ * D1_;
    for (int i = tid; i < OUT_ * D2_; i += 256) w3S[i] = W_d3[i];
    __syncthreads();

    // d2 = relu(d1 @ W_d2^T + b_d2)
    {
        int r = tid >> 2, c0 = (tid & 3) * 16;
        for (int c = c0; c < c0 + 16; c++) {
            float a = __ldg(b_d2 + c);
            const float4* dp = (const float4*)(d1S + r * D1_);
            const float4* wp = (const float4*)(wdS + c * D1_);
#pragma unroll 8
            for (int k4 = 0; k4 < D1_ / 4; k4++) {
                float4 l = dp[k4], w = wp[k4];
                a = fmaf(l.x, w.x, fmaf(l.y, w.y, fmaf(l.z, w.z, fmaf(l.w, w.w, a))));
            }
            d2S[r * D2_ + c] = fmaxf(a, 0.0f);
        }
    }
    __syncthreads();

    // out = d2 @ W_d3^T + b_d3
    for (int idx = tid; idx < 64 * OUT_; idx += 256) {
        int r = idx / OUT_, c = idx % OUT_;
        float a = __ldg(b_d3 + c);
        const float* dp = d2S + r * D2_;
        const float* wp = w3S + c * D2_;
#pragma unroll 8
        for (int k = 0; k < D2_; k++) a = fmaf(dp[k], wp[k], a);
        out[(row0 + r) * OUT_ + c] = a;
    }
}

// ======================= launch =======================
extern "C" void kernel_launch(void* const* d_in, const int* in_sizes, int n_in,
                              void* d_out, int out_size) {
    (void)in_sizes; (void)n_in; (void)out_size;
    const float* x     = (const float*)d_in[0];
    const float* W_in  = (const float*)d_in[1];
    const float* b_in  = (const float*)d_in[2];
    const float* g_in  = (const float*)d_in[3];
    const float* be_in = (const float*)d_in[4];
    const float* Wih0  = (const float*)d_in[5];
    const float* Whh0  = (const float*)d_in[6];
    const float* bih0  = (const float*)d_in[7];
    const float* bhh0  = (const float*)d_in[8];
    const float* Wih1  = (const float*)d_in[9];
    const float* Whh1  = (const float*)d_in[10];
    const float* bih1  = (const float*)d_in[11];
    const float* bhh1  = (const float*)d_in[12];
    const float* g_ln  = (const float*)d_in[13];
    const float* be_ln = (const float*)d_in[14];
    const float* W_d1  = (const float*)d_in[15];
    const float* b_d1  = (const float*)d_in[16];
    const float* W_d2  = (const float*)d_in[17];
    const float* b_d2  = (const float*)d_in[18];
    const float* W_d3  = (const float*)d_in[19];
    const float* b_d3  = (const float*)d_in[20];
    float* out = (float*)d_out;

    prep_kernel<<<1024, 256>>>(Wih0, Whh0, bih0, bhh0, Wih1, Whh1, bih1, bhh1);
    proj_ln_kernel<<<(B_ * T_) / 8, 256>>>(x, W_in, b_in, g_in, be_in);
    cudaFuncSetAttribute(lstm_kernel, cudaFuncAttributeMaxDynamicSharedMemorySize, SMEM_BYTES);
    lstm_kernel<<<B_ / 64, 256, SMEM_BYTES>>>(g_ln, be_ln, W_d1, b_d1, W_d2, b_d2,
                                              W_d3, b_d3, out);
}